// round 5
// baseline (speedup 1.0000x reference)
#include <cuda_runtime.h>
#include <cuda_bf16.h>
#include <cstdint>
#include <math.h>

#define BB 32
#define NN 1024
#define HH 256
#define AA 32
#define OO 256
#define MM (BB*NN)   // 32768 particle rows

// ---------------- scratch (static device arrays; no allocation) -------------
__device__ float g_U  [MM*HH];
__device__ float g_NXT[MM*HH];
__device__ float g_llpart[2*MM];
__device__ int   g_idx[MM];
__device__ float g_partial[BB*128*HH];

// bf16 hi/lo split operands
__device__ __align__(128) __nv_bfloat16 g_Phi [MM*HH], g_Plo [MM*HH];
__device__ __align__(128) __nv_bfloat16 g_XRhi[MM*HH], g_XRlo[MM*HH];
__device__ __align__(128) __nv_bfloat16 g_NXhi[MM*HH], g_NXlo[MM*HH];
__device__ __align__(128) __nv_bfloat16 g_Z1hi[MM*HH], g_Z1lo[MM*HH];
__device__ __align__(128) __nv_bfloat16 g_ACThi[BB*AA], g_ACTlo[BB*AA];
__device__ __align__(128) __nv_bfloat16 g_OBShi[BB*OO], g_OBSlo[BB*OO];

#define WT_TOTAL 417792
__device__ __align__(128) __nv_bfloat16 g_WT_hi[WT_TOTAL];
__device__ __align__(128) __nv_bfloat16 g_WT_lo[WT_TOTAL];
// offsets: Wr 0, Wu 73728, Wc 147456, W0 221184, W1 352256

__device__ __forceinline__ float sigmoid_f(float x){ return 1.0f/(1.0f+expf(-x)); }
__device__ __forceinline__ float gelu_f(float x){ return 0.5f*x*(1.0f+erff(x*0.70710678118654752f)); }

__device__ __forceinline__ void split2(float x, float y, uint32_t& hi, uint32_t& lo){
    __nv_bfloat16 hx = __float2bfloat16_rn(x), hy = __float2bfloat16_rn(y);
    __nv_bfloat16 lx = __float2bfloat16_rn(x - __bfloat162float(hx));
    __nv_bfloat16 ly = __float2bfloat16_rn(y - __bfloat162float(hy));
    hi = (uint32_t)__bfloat16_as_ushort(hx) | ((uint32_t)__bfloat16_as_ushort(hy) << 16);
    lo = (uint32_t)__bfloat16_as_ushort(lx) | ((uint32_t)__bfloat16_as_ushort(ly) << 16);
}

__device__ __forceinline__ void mma16816(float* c, const uint32_t* a, uint32_t b0, uint32_t b1){
    asm volatile("mma.sync.aligned.m16n8k16.row.col.f32.bf16.bf16.f32 "
        "{%0,%1,%2,%3}, {%4,%5,%6,%7}, {%8,%9}, {%0,%1,%2,%3};"
        : "+f"(c[0]), "+f"(c[1]), "+f"(c[2]), "+f"(c[3])
        : "r"(a[0]), "r"(a[1]), "r"(a[2]), "r"(a[3]), "r"(b0), "r"(b1));
}

__device__ __forceinline__ uint32_t smem_u32(const void* p){
    uint32_t a;
    asm("{ .reg .u64 t; cvta.to.shared.u64 t, %1; cvt.u32.u64 %0, t; }" : "=r"(a) : "l"(p));
    return a;
}

#define CP16(dst, src) \
    asm volatile("cp.async.cg.shared.global [%0], [%1], 16;" :: "r"(dst), "l"(src) : "memory")
#define CP_COMMIT() asm volatile("cp.async.commit_group;" ::: "memory")
#define CP_WAIT2()  asm volatile("cp.async.wait_group 2;" ::: "memory")
#define CP_WAIT1()  asm volatile("cp.async.wait_group 1;" ::: "memory")
#define CP_WAIT0()  asm volatile("cp.async.wait_group 0;" ::: "memory")
#define LDM4(r0,r1,r2,r3,addr) \
    asm volatile("ldmatrix.sync.aligned.m8n8.x4.shared.b16 {%0,%1,%2,%3}, [%4];" \
        : "=r"(r0),"=r"(r1),"=r"(r2),"=r"(r3) : "r"(addr))

#define PITCH 80
#define TILE_M 256
// stage: Ahi 256*80=20480 | Alo 20480 | Bhi 128*80=10240 | Blo 10240
#define OFF_ALO 20480
#define OFF_BHI 40960
#define OFF_BLO 51200
#define STAGE_STRIDE 61440
#define NSTAGE 3
#define SMEM_BYTES (NSTAGE*STAGE_STRIDE)

// ---------------------------------------------------------------------------
// Prep kernels
// ---------------------------------------------------------------------------
__global__ void wprep_k(const float* __restrict__ Wr, const float* __restrict__ Wu,
                        const float* __restrict__ Wc, const float* __restrict__ W0,
                        const float* __restrict__ W1)
{
    const int mid = blockIdx.z;
    const int Ks[5] = {288,288,288,512,256};
    const size_t offs[5] = {0,73728,147456,221184,352256};
    const float* src = (mid==0)?Wr:(mid==1)?Wu:(mid==2)?Wc:(mid==3)?W0:W1;
    const int K = Ks[mid];
    const int k0 = blockIdx.x * 32;
    if (k0 >= K) return;
    const int n0 = blockIdx.y * 32;
    const int tx = threadIdx.x, ty = threadIdx.y;

    __shared__ float tile[32][33];
#pragma unroll
    for (int i=0;i<4;i++)
        tile[ty*4+i][tx] = src[(size_t)(k0+ty*4+i)*HH + n0 + tx];
    __syncthreads();
#pragma unroll
    for (int i=0;i<4;i++){
        const int r = ty*4+i;
        const float v = tile[tx][r];
        __nv_bfloat16 h = __float2bfloat16_rn(v);
        __nv_bfloat16 l = __float2bfloat16_rn(v - __bfloat162float(h));
        const size_t o = offs[mid] + (size_t)(n0+r)*K + k0 + tx;
        g_WT_hi[o] = h;
        g_WT_lo[o] = l;
    }
}

__global__ void psplit_k(const float* __restrict__ p)
{
    const size_t i = ((size_t)blockIdx.x * 256 + threadIdx.x) * 4;
    float4 v = *(const float4*)(p + i);
    uint32_t h0,l0,h1,l1;
    split2(v.x, v.y, h0, l0);
    split2(v.z, v.w, h1, l1);
    *(uint2*)&g_Phi[i] = make_uint2(h0, h1);
    *(uint2*)&g_Plo[i] = make_uint2(l0, l1);
}

__global__ void ssplit_k(const float* __restrict__ act, const float* __restrict__ obs)
{
    for (int i = threadIdx.x; i < BB*AA; i += 256){
        float v = act[i];
        __nv_bfloat16 h = __float2bfloat16_rn(v);
        g_ACThi[i] = h;
        g_ACTlo[i] = __float2bfloat16_rn(v - __bfloat162float(h));
    }
    for (int i = threadIdx.x; i < BB*OO; i += 256){
        float v = obs[i];
        __nv_bfloat16 h = __float2bfloat16_rn(v);
        g_OBShi[i] = h;
        g_OBSlo[i] = __float2bfloat16_rn(v - __bfloat162float(h));
    }
}

// ---------------------------------------------------------------------------
// HMMA GEMM: 512 threads, CTA tile 256x128, 3-stage cp.async pipeline.
// warps: 8M x 2N, warp tile 32x64. bf16 3-term hi/lo split.
// ---------------------------------------------------------------------------
template<int MODE>
__device__ __forceinline__ void stage_panel(
    uint32_t buf, int p, int tid, int m0,
    const __nv_bfloat16* __restrict__ aHi, const __nv_bfloat16* __restrict__ aLo,
    const __nv_bfloat16* __restrict__ tHi, const __nv_bfloat16* __restrict__ tLo,
    const __nv_bfloat16* __restrict__ wHi, const __nv_bfloat16* __restrict__ wLo, int K)
{
    const int k0 = p * 32;
#pragma unroll
    for (int i=0;i<2;i++){
        const int idx = tid + i*512;
        const int row = idx >> 2, seg = idx & 3;
        const int k   = k0 + seg*8;
        const __nv_bfloat16 *sh, *sl;
        if (MODE==4 || k < 256){
            sh = aHi + (size_t)(m0+row)*HH + k;
            sl = aLo + (size_t)(m0+row)*HH + k;
        } else {
            sh = tHi + (k - 256);
            sl = tLo + (k - 256);
        }
        const uint32_t d = (uint32_t)(row*PITCH + seg*16);
        CP16(buf + d,           sh);
        CP16(buf + OFF_ALO + d, sl);
    }
    {
        const int row = tid >> 2, seg = tid & 3;
        const __nv_bfloat16* sh = wHi + (size_t)row*K + k0 + seg*8;
        const __nv_bfloat16* sl = wLo + (size_t)row*K + k0 + seg*8;
        const uint32_t d = (uint32_t)(row*PITCH + seg*16);
        CP16(buf + OFF_BHI + d, sh);
        CP16(buf + OFF_BLO + d, sl);
    }
}

template<int MODE>
__global__ void __launch_bounds__(512, 1) hmma_gemm_k(
    const float* __restrict__ particles,
    const float* __restrict__ br, const float* __restrict__ bu,
    const float* __restrict__ bc, const float* __restrict__ b0,
    const float* __restrict__ b1, const float* __restrict__ W2)
{
    constexpr int K = (MODE==1 || MODE==2) ? 288 : (MODE==3 ? 512 : 256);
    constexpr int P = K / 32;

    extern __shared__ __align__(128) char smem[];
    const uint32_t sbase = smem_u32(smem);

    const int tid  = threadIdx.x;
    const int wid  = tid >> 5;
    const int lane = tid & 31;
    const int g    = lane >> 2;
    const int tig  = lane & 3;
    const int t8   = lane >> 3;
    const int r8   = lane & 7;
    const int warpM = wid >> 1;     // 0..7
    const int warpN = wid & 1;      // 0..1
    const int m0   = blockIdx.y * TILE_M;
    const int bidx = blockIdx.y >> 2;

    size_t wt_off; int nw0;
    if (MODE==1){ wt_off = (blockIdx.x < 2) ? 0 : 73728; nw0 = (blockIdx.x & 1) * 128; }
    else if (MODE==2){ wt_off = 147456; nw0 = blockIdx.x * 128; }
    else if (MODE==3){ wt_off = 221184; nw0 = blockIdx.x * 128; }
    else             { wt_off = 352256; nw0 = blockIdx.x * 128; }

    const __nv_bfloat16* aHi = (MODE==1) ? g_Phi : (MODE==2) ? g_XRhi : (MODE==3) ? g_NXhi : g_Z1hi;
    const __nv_bfloat16* aLo = (MODE==1) ? g_Plo : (MODE==2) ? g_XRlo : (MODE==3) ? g_NXlo : g_Z1lo;
    const __nv_bfloat16* tHi = (MODE==3) ? (g_OBShi + bidx*OO) : (g_ACThi + bidx*AA);
    const __nv_bfloat16* tLo = (MODE==3) ? (g_OBSlo + bidx*OO) : (g_ACTlo + bidx*AA);
    const __nv_bfloat16* wHi = g_WT_hi + wt_off + (size_t)nw0 * K;
    const __nv_bfloat16* wLo = g_WT_lo + wt_off + (size_t)nw0 * K;

    float acc[2][8][4];
#pragma unroll
    for (int i=0;i<2;i++)
#pragma unroll
        for (int j=0;j<8;j++)
#pragma unroll
            for (int q=0;q<4;q++) acc[i][j][q] = 0.f;

    stage_panel<MODE>(sbase + 0*STAGE_STRIDE, 0, tid, m0, aHi,aLo,tHi,tLo,wHi,wLo,K); CP_COMMIT();
    stage_panel<MODE>(sbase + 1*STAGE_STRIDE, 1, tid, m0, aHi,aLo,tHi,tLo,wHi,wLo,K); CP_COMMIT();
    stage_panel<MODE>(sbase + 2*STAGE_STRIDE, 2, tid, m0, aHi,aLo,tHi,tLo,wHi,wLo,K); CP_COMMIT();

    int slot = 0;
#pragma unroll 1
    for (int p = 0; p < P; ++p){
        if      (p <= P-3) { CP_WAIT2(); }
        else if (p == P-2) { CP_WAIT1(); }
        else               { CP_WAIT0(); }
        __syncthreads();

        const uint32_t base = sbase + slot * STAGE_STRIDE;
        const uint32_t aHiS = base, aLoS = base + OFF_ALO;
        const uint32_t bHiS = base + OFF_BHI, bLoS = base + OFF_BLO;

#pragma unroll
        for (int ks = 0; ks < 2; ++ks){
            const int kkb = ks * 32;
            uint32_t ah[2][4], al[2][4];
#pragma unroll
            for (int mf = 0; mf < 2; ++mf){
                const uint32_t off = (uint32_t)((warpM*32 + mf*16 + (t8&1)*8 + r8)*PITCH
                                                + ((t8>>1)*8)*2 + kkb);
                LDM4(ah[mf][0],ah[mf][1],ah[mf][2],ah[mf][3], aHiS + off);
                LDM4(al[mf][0],al[mf][1],al[mf][2],al[mf][3], aLoS + off);
            }
#pragma unroll
            for (int q = 0; q < 4; ++q){
                const uint32_t boff = (uint32_t)((warpN*64 + q*16 + (t8>>1)*8 + r8)*PITCH
                                                 + ((t8&1)*8)*2 + kkb);
                uint32_t b0_,b1_,b2_,b3_, c0_,c1_,c2_,c3_;
                LDM4(b0_,b1_,b2_,b3_, bHiS + boff);
                LDM4(c0_,c1_,c2_,c3_, bLoS + boff);
                // term-major issue: RAW distance 4 on every accumulator
                mma16816(acc[0][2*q],   ah[0], b0_, b1_);
                mma16816(acc[1][2*q],   ah[1], b0_, b1_);
                mma16816(acc[0][2*q+1], ah[0], b2_, b3_);
                mma16816(acc[1][2*q+1], ah[1], b2_, b3_);
                mma16816(acc[0][2*q],   al[0], b0_, b1_);
                mma16816(acc[1][2*q],   al[1], b0_, b1_);
                mma16816(acc[0][2*q+1], al[0], b2_, b3_);
                mma16816(acc[1][2*q+1], al[1], b2_, b3_);
                mma16816(acc[0][2*q],   ah[0], c0_, c1_);
                mma16816(acc[1][2*q],   ah[1], c0_, c1_);
                mma16816(acc[0][2*q+1], ah[0], c2_, c3_);
                mma16816(acc[1][2*q+1], ah[1], c2_, c3_);
            }
        }
        __syncthreads();
        if (p + 3 < P){
            stage_panel<MODE>(sbase + slot*STAGE_STRIDE, p + 3, tid, m0,
                              aHi,aLo,tHi,tLo,wHi,wLo,K);
            CP_COMMIT();
        }
        slot = (slot + 1 == NSTAGE) ? 0 : slot + 1;
    }

    // ---------------- epilogue ----------------
    if (MODE == 4){
        float* red = (float*)smem;   // [256][2]
        float pr[2][2] = {{0.f,0.f},{0.f,0.f}};
#pragma unroll
        for (int mf=0; mf<2; ++mf){
#pragma unroll
            for (int nf=0; nf<8; ++nf){
                const int nc = nw0 + warpN*64 + nf*8 + tig*2;
                const float2 bv = *(const float2*)(b1 + nc);
                const float2 wv = *(const float2*)(W2 + nc);
                float* c = acc[mf][nf];
                pr[mf][0] += gelu_f(c[0]+bv.x)*wv.x + gelu_f(c[1]+bv.y)*wv.y;
                pr[mf][1] += gelu_f(c[2]+bv.x)*wv.x + gelu_f(c[3]+bv.y)*wv.y;
            }
        }
        __syncthreads();
#pragma unroll
        for (int mf=0; mf<2; ++mf)
#pragma unroll
            for (int rr=0; rr<2; ++rr){
                float v = pr[mf][rr];
                v += __shfl_xor_sync(0xffffffffu, v, 1);
                v += __shfl_xor_sync(0xffffffffu, v, 2);
                if (tig == 0) red[(warpM*32 + mf*16 + rr*8 + g)*2 + warpN] = v;
            }
        __syncthreads();
        if (tid < 256)
            g_llpart[(size_t)blockIdx.x*MM + m0 + tid] = red[tid*2] + red[tid*2+1];
        return;
    }

    const float* bias;
    if (MODE==1) bias = (blockIdx.x<2) ? br : bu;
    else if (MODE==2) bias = bc;
    else bias = b0;
    const bool isR = (MODE==1) && (blockIdx.x < 2);

#pragma unroll
    for (int mf=0; mf<2; ++mf){
#pragma unroll
        for (int nf=0; nf<8; ++nf){
            const int nc = nw0 + warpN*64 + nf*8 + tig*2;
            const int m1_ = m0 + warpM*32 + mf*16 + g;
            const int m2_ = m1_ + 8;
            const float2 bv = *(const float2*)(bias + nc);
            float* c = acc[mf][nf];
            if (MODE==1){
                const float s0 = sigmoid_f(c[0]+bv.x), s1 = sigmoid_f(c[1]+bv.y);
                const float s2 = sigmoid_f(c[2]+bv.x), s3 = sigmoid_f(c[3]+bv.y);
                if (isR){
                    const float2 p1 = *(const float2*)(particles + (size_t)m1_*HH + nc);
                    const float2 p2 = *(const float2*)(particles + (size_t)m2_*HH + nc);
                    uint32_t h,l;
                    split2(p1.x*s0, p1.y*s1, h, l);
                    *(uint32_t*)&g_XRhi[(size_t)m1_*HH+nc] = h;
                    *(uint32_t*)&g_XRlo[(size_t)m1_*HH+nc] = l;
                    split2(p2.x*s2, p2.y*s3, h, l);
                    *(uint32_t*)&g_XRhi[(size_t)m2_*HH+nc] = h;
                    *(uint32_t*)&g_XRlo[(size_t)m2_*HH+nc] = l;
                } else {
                    *(float2*)(g_U + (size_t)m1_*HH + nc) = make_float2(s0, s1);
                    *(float2*)(g_U + (size_t)m2_*HH + nc) = make_float2(s2, s3);
                }
            } else if (MODE==2){
                const float2 u1 = *(const float2*)(g_U + (size_t)m1_*HH + nc);
                const float2 u2 = *(const float2*)(g_U + (size_t)m2_*HH + nc);
                const float2 p1 = *(const float2*)(particles + (size_t)m1_*HH + nc);
                const float2 p2 = *(const float2*)(particles + (size_t)m2_*HH + nc);
                float2 r1, r2;
                r1.x = (1.f-u1.x)*p1.x + u1.x*tanhf(c[0]+bv.x);
                r1.y = (1.f-u1.y)*p1.y + u1.y*tanhf(c[1]+bv.y);
                r2.x = (1.f-u2.x)*p2.x + u2.x*tanhf(c[2]+bv.x);
                r2.y = (1.f-u2.y)*p2.y + u2.y*tanhf(c[3]+bv.y);
                *(float2*)(g_NXT + (size_t)m1_*HH + nc) = r1;
                *(float2*)(g_NXT + (size_t)m2_*HH + nc) = r2;
                uint32_t h,l;
                split2(r1.x, r1.y, h, l);
                *(uint32_t*)&g_NXhi[(size_t)m1_*HH+nc] = h;
                *(uint32_t*)&g_NXlo[(size_t)m1_*HH+nc] = l;
                split2(r2.x, r2.y, h, l);
                *(uint32_t*)&g_NXhi[(size_t)m2_*HH+nc] = h;
                *(uint32_t*)&g_NXlo[(size_t)m2_*HH+nc] = l;
            } else {
                const float z0 = gelu_f(c[0]+bv.x), z1_ = gelu_f(c[1]+bv.y);
                const float z2 = gelu_f(c[2]+bv.x), z3 = gelu_f(c[3]+bv.y);
                uint32_t h,l;
                split2(z0, z1_, h, l);
                *(uint32_t*)&g_Z1hi[(size_t)m1_*HH+nc] = h;
                *(uint32_t*)&g_Z1lo[(size_t)m1_*HH+nc] = l;
                split2(z2, z3, h, l);
                *(uint32_t*)&g_Z1hi[(size_t)m2_*HH+nc] = h;
                *(uint32_t*)&g_Z1lo[(size_t)m2_*HH+nc] = l;
            }
        }
    }
}

// ---------------------------------------------------------------------------
__global__ void __launch_bounds__(NN) stage_weights_k(
    const float* __restrict__ weights,
    const float* __restrict__ uin,
    const float* __restrict__ b2,
    float* __restrict__ dout)
{
    __shared__ float sh[NN];
    const int b = blockIdx.x;
    const int n = threadIdx.x;
    const int m = b*NN + n;

    const float ll = g_llpart[m] + g_llpart[MM + m] + b2[0];
    const float lw = logf(weights[m] + 1e-10f) + ll;

    sh[n] = lw; __syncthreads();
    for (int s=512; s>0; s>>=1) { if (n<s) sh[n] = fmaxf(sh[n], sh[n+s]); __syncthreads(); }
    const float mx = sh[0]; __syncthreads();

    const float e = expf(lw - mx);
    sh[n] = e; __syncthreads();
    for (int s=512; s>0; s>>=1) { if (n<s) sh[n] += sh[n+s]; __syncthreads(); }
    const float S = sh[0]; __syncthreads();
    const float nw = e / S;

    sh[n] = nw*nw; __syncthreads();
    for (int s=512; s>0; s>>=1) { if (n<s) sh[n] += sh[n+s]; __syncthreads(); }
    const float ess = 1.0f / (sh[0] + 1e-10f); __syncthreads();
    const bool should = ess < 0.5f * (float)NN;

    float val = nw;
    sh[n] = val; __syncthreads();
    for (int off=1; off<NN; off<<=1) {
        float add = (n>=off) ? sh[n-off] : 0.f;
        __syncthreads();
        val += add;
        sh[n] = val;
        __syncthreads();
    }

    float pos = uin[b]*(1.0f/(float)NN) + (float)n*(1.0f/(float)NN);
    pos = fminf(pos, 0.9999f);
    int lo = 0, hi = NN;
    while (lo < hi) {
        int mid = (lo + hi) >> 1;
        if (sh[mid] < pos) lo = mid + 1; else hi = mid;
    }
    int idx = lo < (NN-1) ? lo : (NN-1);

    g_idx[m] = should ? idx : n;
    const float wf = should ? (1.0f/(float)NN) : nw;
    dout[8192 + (size_t)MM*HH + m] = wf;
    if (n == 0) dout[8192 + (size_t)MM*HH + MM + b] = ess;
}

__global__ void __launch_bounds__(HH) gather_belief_k(float* __restrict__ dout)
{
    const int b = blockIdx.y;
    const int chunk = blockIdx.x;
    const int h = threadIdx.x;
    const float* dw = dout + 8192 + (size_t)MM*HH;
    float* dnxt = dout + 8192;

    float accp = 0.f;
#pragma unroll
    for (int r=0; r<8; r++) {
        const int j = chunk*8 + r;
        const int src = g_idx[b*NN + j];
        const float v = g_NXT[(size_t)(b*NN + src)*HH + h];
        dnxt[(size_t)(b*NN + j)*HH + h] = v;
        accp = fmaf(v, dw[b*NN + j], accp);
    }
    g_partial[(b*128 + chunk)*HH + h] = accp;
}

__global__ void __launch_bounds__(HH) belief_reduce_k(float* __restrict__ dout)
{
    const int b = blockIdx.x;
    const int h = threadIdx.x;
    float s = 0.f;
    for (int c=0; c<128; c++) s += g_partial[(b*128 + c)*HH + h];
    dout[b*HH + h] = s;
}

// ---------------------------------------------------------------------------
extern "C" void kernel_launch(void* const* d_in, const int* in_sizes, int n_in,
                              void* d_out, int out_size)
{
    (void)in_sizes; (void)n_in; (void)out_size;
    const float* particles   = (const float*)d_in[0];
    const float* weights     = (const float*)d_in[1];
    const float* action      = (const float*)d_in[2];
    const float* observation = (const float*)d_in[3];
    const float* uin         = (const float*)d_in[4];
    const float* Wr = (const float*)d_in[5];  const float* br = (const float*)d_in[6];
    const float* Wu = (const float*)d_in[7];  const float* bu = (const float*)d_in[8];
    const float* Wc = (const float*)d_in[9];  const float* bc = (const float*)d_in[10];
    const float* W0 = (const float*)d_in[11]; const float* b0 = (const float*)d_in[12];
    const float* W1 = (const float*)d_in[13]; const float* b1 = (const float*)d_in[14];
    const float* W2 = (const float*)d_in[15]; const float* b2 = (const float*)d_in[16];
    float* out = (float*)d_out;

    cudaFuncSetAttribute(hmma_gemm_k<1>, cudaFuncAttributeMaxDynamicSharedMemorySize, SMEM_BYTES);
    cudaFuncSetAttribute(hmma_gemm_k<2>, cudaFuncAttributeMaxDynamicSharedMemorySize, SMEM_BYTES);
    cudaFuncSetAttribute(hmma_gemm_k<3>, cudaFuncAttributeMaxDynamicSharedMemorySize, SMEM_BYTES);
    cudaFuncSetAttribute(hmma_gemm_k<4>, cudaFuncAttributeMaxDynamicSharedMemorySize, SMEM_BYTES);

    wprep_k<<<dim3(16, 8, 5), dim3(32, 8)>>>(Wr, Wu, Wc, W0, W1);
    psplit_k<<<(MM*HH)/1024, 256>>>(particles);
    ssplit_k<<<1, 256>>>(action, observation);

    const dim3 blk(512);
    hmma_gemm_k<1><<<dim3(4, MM/TILE_M), blk, SMEM_BYTES>>>(particles, br, bu, bc, b0, b1, W2);
    hmma_gemm_k<2><<<dim3(2, MM/TILE_M), blk, SMEM_BYTES>>>(particles, br, bu, bc, b0, b1, W2);
    hmma_gemm_k<3><<<dim3(2, MM/TILE_M), blk, SMEM_BYTES>>>(particles, br, bu, bc, b0, b1, W2);
    hmma_gemm_k<4><<<dim3(2, MM/TILE_M), blk, SMEM_BYTES>>>(particles, br, bu, bc, b0, b1, W2);
    stage_weights_k<<<BB, NN>>>(weights, uin, b2, out);
    gather_belief_k<<<dim3(128, BB), HH>>>(out);
    belief_reduce_k<<<BB, HH>>>(out);
}

// round 6
// speedup vs baseline: 1.2807x; 1.2807x over previous
#include <cuda_runtime.h>
#include <cuda_fp16.h>
#include <cstdint>
#include <math.h>

#define BB 32
#define NN 1024
#define HH 256
#define AA 32
#define OO 256
#define MM (BB*NN)   // 32768 particle rows

// ---------------- scratch (static device arrays; no allocation) -------------
__device__ float g_U  [MM*HH];
__device__ float g_NXT[MM*HH];
__device__ float g_llpart[2*MM];
__device__ int   g_idx[MM];
__device__ float g_partial[BB*128*HH];

// fp16 hi/lo split A operands; single-fp16 B (weights)
__device__ __align__(128) __half g_Phi [MM*HH], g_Plo [MM*HH];
__device__ __align__(128) __half g_XRhi[MM*HH], g_XRlo[MM*HH];
__device__ __align__(128) __half g_NXhi[MM*HH], g_NXlo[MM*HH];
__device__ __align__(128) __half g_Z1hi[MM*HH], g_Z1lo[MM*HH];
__device__ __align__(128) __half g_ACThi[BB*AA], g_ACTlo[BB*AA];
__device__ __align__(128) __half g_OBShi[BB*OO], g_OBSlo[BB*OO];

#define WT_TOTAL 417792
__device__ __align__(128) __half g_WT[WT_TOTAL];
// offsets: Wr 0, Wu 73728, Wc 147456, W0 221184, W1 352256

__device__ __forceinline__ float sigmoid_f(float x){ return 1.0f/(1.0f+expf(-x)); }
__device__ __forceinline__ float gelu_f(float x){ return 0.5f*x*(1.0f+erff(x*0.70710678118654752f)); }

__device__ __forceinline__ void split2h(float x, float y, uint32_t& hi, uint32_t& lo){
    __half hx = __float2half_rn(x), hy = __float2half_rn(y);
    __half lx = __float2half_rn(x - __half2float(hx));
    __half ly = __float2half_rn(y - __half2float(hy));
    hi = (uint32_t)__half_as_ushort(hx) | ((uint32_t)__half_as_ushort(hy) << 16);
    lo = (uint32_t)__half_as_ushort(lx) | ((uint32_t)__half_as_ushort(ly) << 16);
}

__device__ __forceinline__ void mma16816(float* c, const uint32_t* a, uint32_t b0, uint32_t b1){
    asm volatile("mma.sync.aligned.m16n8k16.row.col.f32.f16.f16.f32 "
        "{%0,%1,%2,%3}, {%4,%5,%6,%7}, {%8,%9}, {%0,%1,%2,%3};"
        : "+f"(c[0]), "+f"(c[1]), "+f"(c[2]), "+f"(c[3])
        : "r"(a[0]), "r"(a[1]), "r"(a[2]), "r"(a[3]), "r"(b0), "r"(b1));
}

__device__ __forceinline__ uint32_t smem_u32(const void* p){
    uint32_t a;
    asm("{ .reg .u64 t; cvta.to.shared.u64 t, %1; cvt.u32.u64 %0, t; }" : "=r"(a) : "l"(p));
    return a;
}

#define CP16(dst, src) \
    asm volatile("cp.async.cg.shared.global [%0], [%1], 16;" :: "r"(dst), "l"(src) : "memory")
#define CP_COMMIT() asm volatile("cp.async.commit_group;" ::: "memory")
#define CP_WAIT1()  asm volatile("cp.async.wait_group 1;" ::: "memory")
#define CP_WAIT0()  asm volatile("cp.async.wait_group 0;" ::: "memory")
#define LDM4(r0,r1,r2,r3,addr) \
    asm volatile("ldmatrix.sync.aligned.m8n8.x4.shared.b16 {%0,%1,%2,%3}, [%4];" \
        : "=r"(r0),"=r"(r1),"=r"(r2),"=r"(r3) : "r"(addr))

#define PITCH 80
// stage: Ahi 128*80=10240 | Alo 10240 | B 10240
#define OFF_ALO 10240
#define OFF_B   20480
#define STAGE_STRIDE 30720
#define SMEM_BYTES  (2*STAGE_STRIDE)

// ---------------------------------------------------------------------------
// Prep kernels
// ---------------------------------------------------------------------------
__global__ void wprep_k(const float* __restrict__ Wr, const float* __restrict__ Wu,
                        const float* __restrict__ Wc, const float* __restrict__ W0,
                        const float* __restrict__ W1)
{
    const int mid = blockIdx.z;
    const int Ks[5] = {288,288,288,512,256};
    const size_t offs[5] = {0,73728,147456,221184,352256};
    const float* src = (mid==0)?Wr:(mid==1)?Wu:(mid==2)?Wc:(mid==3)?W0:W1;
    const int K = Ks[mid];
    const int k0 = blockIdx.x * 32;
    if (k0 >= K) return;
    const int n0 = blockIdx.y * 32;
    const int tx = threadIdx.x, ty = threadIdx.y;

    __shared__ float tile[32][33];
#pragma unroll
    for (int i=0;i<4;i++)
        tile[ty*4+i][tx] = src[(size_t)(k0+ty*4+i)*HH + n0 + tx];
    __syncthreads();
#pragma unroll
    for (int i=0;i<4;i++){
        const int r = ty*4+i;
        g_WT[offs[mid] + (size_t)(n0+r)*K + k0 + tx] = __float2half_rn(tile[tx][r]);
    }
}

__global__ void psplit_k(const float* __restrict__ p)
{
    const size_t i = ((size_t)blockIdx.x * 256 + threadIdx.x) * 4;
    float4 v = *(const float4*)(p + i);
    uint32_t h0,l0,h1,l1;
    split2h(v.x, v.y, h0, l0);
    split2h(v.z, v.w, h1, l1);
    *(uint2*)&g_Phi[i] = make_uint2(h0, h1);
    *(uint2*)&g_Plo[i] = make_uint2(l0, l1);
}

__global__ void ssplit_k(const float* __restrict__ act, const float* __restrict__ obs)
{
    for (int i = threadIdx.x; i < BB*AA; i += 256){
        float v = act[i];
        __half h = __float2half_rn(v);
        g_ACThi[i] = h;
        g_ACTlo[i] = __float2half_rn(v - __half2float(h));
    }
    for (int i = threadIdx.x; i < BB*OO; i += 256){
        float v = obs[i];
        __half h = __float2half_rn(v);
        g_OBShi[i] = h;
        g_OBSlo[i] = __float2half_rn(v - __half2float(h));
    }
}

// ---------------------------------------------------------------------------
// HMMA GEMM: fp16 2-term (A hi/lo, B single), cp.async double-buffer, ldmatrix.
// CTA tile 128x128, 256 threads = 8 warps (4M x 2N), warp tile 32x64.
// ---------------------------------------------------------------------------
template<int MODE>
__device__ __forceinline__ void stage_panel(
    uint32_t buf, int p, int tid, int m0,
    const __half* __restrict__ aHi, const __half* __restrict__ aLo,
    const __half* __restrict__ tHi, const __half* __restrict__ tLo,
    const __half* __restrict__ w, int K)
{
    const int k0 = p * 32;
#pragma unroll
    for (int i=0;i<2;i++){
        const int idx = tid + i*256;
        const int row = idx >> 2, seg = idx & 3;
        const int k   = k0 + seg*8;
        const __half *sh, *sl;
        if (MODE==4 || k < 256){
            sh = aHi + (size_t)(m0+row)*HH + k;
            sl = aLo + (size_t)(m0+row)*HH + k;
        } else {
            sh = tHi + (k - 256);
            sl = tLo + (k - 256);
        }
        const uint32_t d = (uint32_t)(row*PITCH + seg*16);
        CP16(buf + d,           sh);
        CP16(buf + OFF_ALO + d, sl);
    }
#pragma unroll
    for (int i=0;i<2;i++){
        const int idx = tid + i*256;
        const int row = idx >> 2, seg = idx & 3;
        const __half* s = w + (size_t)row*K + k0 + seg*8;
        CP16(buf + OFF_B + (uint32_t)(row*PITCH + seg*16), s);
    }
}

template<int MODE>
__global__ void __launch_bounds__(256, 2) hmma_gemm_k(
    const float* __restrict__ particles,
    const float* __restrict__ br, const float* __restrict__ bu,
    const float* __restrict__ bc, const float* __restrict__ b0,
    const float* __restrict__ b1, const float* __restrict__ W2)
{
    constexpr int K = (MODE==1 || MODE==2) ? 288 : (MODE==3 ? 512 : 256);
    constexpr int P = K / 32;

    extern __shared__ __align__(128) char smem[];
    __shared__ float red[128][2];
    const uint32_t sbase = smem_u32(smem);

    const int tid  = threadIdx.x;
    const int wid  = tid >> 5;
    const int lane = tid & 31;
    const int g    = lane >> 2;
    const int tig  = lane & 3;
    const int t8   = lane >> 3;
    const int r8   = lane & 7;
    const int warpM = wid >> 1;
    const int warpN = wid & 1;
    const int m0   = blockIdx.y * 128;
    const int bidx = blockIdx.y >> 3;

    size_t wt_off; int nw0;
    if (MODE==1){ wt_off = (blockIdx.x < 2) ? 0 : 73728; nw0 = (blockIdx.x & 1) * 128; }
    else if (MODE==2){ wt_off = 147456; nw0 = blockIdx.x * 128; }
    else if (MODE==3){ wt_off = 221184; nw0 = blockIdx.x * 128; }
    else             { wt_off = 352256; nw0 = blockIdx.x * 128; }

    const __half* aHi = (MODE==1) ? g_Phi : (MODE==2) ? g_XRhi : (MODE==3) ? g_NXhi : g_Z1hi;
    const __half* aLo = (MODE==1) ? g_Plo : (MODE==2) ? g_XRlo : (MODE==3) ? g_NXlo : g_Z1lo;
    const __half* tHi = (MODE==3) ? (g_OBShi + bidx*OO) : (g_ACThi + bidx*AA);
    const __half* tLo = (MODE==3) ? (g_OBSlo + bidx*OO) : (g_ACTlo + bidx*AA);
    const __half* w   = g_WT + wt_off + (size_t)nw0 * K;

    float acc[2][8][4];
#pragma unroll
    for (int i=0;i<2;i++)
#pragma unroll
        for (int j=0;j<8;j++)
#pragma unroll
            for (int q=0;q<4;q++) acc[i][j][q] = 0.f;

    stage_panel<MODE>(sbase,                0, tid, m0, aHi,aLo,tHi,tLo,w,K); CP_COMMIT();
    stage_panel<MODE>(sbase + STAGE_STRIDE, 1, tid, m0, aHi,aLo,tHi,tLo,w,K); CP_COMMIT();

#pragma unroll 1
    for (int p = 0; p < P; ++p){
        if (p + 1 < P) { CP_WAIT1(); } else { CP_WAIT0(); }
        __syncthreads();

        const uint32_t base = sbase + (p & 1) * STAGE_STRIDE;
        const uint32_t aHiS = base, aLoS = base + OFF_ALO, bS = base + OFF_B;

#pragma unroll
        for (int ks = 0; ks < 2; ++ks){
            const int kkb = ks * 32;
            uint32_t ah[2][4], al[2][4];
#pragma unroll
            for (int mf = 0; mf < 2; ++mf){
                const uint32_t off = (uint32_t)((warpM*32 + mf*16 + (t8&1)*8 + r8)*PITCH
                                                + ((t8>>1)*8)*2 + kkb);
                LDM4(ah[mf][0],ah[mf][1],ah[mf][2],ah[mf][3], aHiS + off);
                LDM4(al[mf][0],al[mf][1],al[mf][2],al[mf][3], aLoS + off);
            }
#pragma unroll
            for (int q = 0; q < 4; ++q){
                const uint32_t boff = (uint32_t)((warpN*64 + q*16 + (t8>>1)*8 + r8)*PITCH
                                                 + ((t8&1)*8)*2 + kkb);
                uint32_t b0_,b1_,b2_,b3_;
                LDM4(b0_,b1_,b2_,b3_, bS + boff);
                // term-major: RAW distance 4 per accumulator
                mma16816(acc[0][2*q],   ah[0], b0_, b1_);
                mma16816(acc[1][2*q],   ah[1], b0_, b1_);
                mma16816(acc[0][2*q+1], ah[0], b2_, b3_);
                mma16816(acc[1][2*q+1], ah[1], b2_, b3_);
                mma16816(acc[0][2*q],   al[0], b0_, b1_);
                mma16816(acc[1][2*q],   al[1], b0_, b1_);
                mma16816(acc[0][2*q+1], al[0], b2_, b3_);
                mma16816(acc[1][2*q+1], al[1], b2_, b3_);
            }
        }
        __syncthreads();
        if (p + 2 < P){
            stage_panel<MODE>(sbase + (p & 1)*STAGE_STRIDE, p + 2, tid, m0,
                              aHi,aLo,tHi,tLo,w,K);
            CP_COMMIT();
        }
    }

    // ---------------- epilogue ----------------
    if (MODE == 4){
        float pr[2][2] = {{0.f,0.f},{0.f,0.f}};
#pragma unroll
        for (int mf=0; mf<2; ++mf){
#pragma unroll
            for (int nf=0; nf<8; ++nf){
                const int nc = nw0 + warpN*64 + nf*8 + tig*2;
                const float2 bv = *(const float2*)(b1 + nc);
                const float2 wv = *(const float2*)(W2 + nc);
                float* c = acc[mf][nf];
                pr[mf][0] += gelu_f(c[0]+bv.x)*wv.x + gelu_f(c[1]+bv.y)*wv.y;
                pr[mf][1] += gelu_f(c[2]+bv.x)*wv.x + gelu_f(c[3]+bv.y)*wv.y;
            }
        }
#pragma unroll
        for (int mf=0; mf<2; ++mf)
#pragma unroll
            for (int rr=0; rr<2; ++rr){
                float v = pr[mf][rr];
                v += __shfl_xor_sync(0xffffffffu, v, 1);
                v += __shfl_xor_sync(0xffffffffu, v, 2);
                if (tig == 0) red[warpM*32 + mf*16 + rr*8 + g][warpN] = v;
            }
        __syncthreads();
        if (tid < 128)
            g_llpart[(size_t)blockIdx.x*MM + m0 + tid] = red[tid][0] + red[tid][1];
        return;
    }

    const float* bias;
    if (MODE==1) bias = (blockIdx.x<2) ? br : bu;
    else if (MODE==2) bias = bc;
    else bias = b0;
    const bool isR = (MODE==1) && (blockIdx.x < 2);

#pragma unroll
    for (int mf=0; mf<2; ++mf){
#pragma unroll
        for (int nf=0; nf<8; ++nf){
            const int nc = nw0 + warpN*64 + nf*8 + tig*2;
            const int m1_ = m0 + warpM*32 + mf*16 + g;
            const int m2_ = m1_ + 8;
            const float2 bv = *(const float2*)(bias + nc);
            float* c = acc[mf][nf];
            if (MODE==1){
                const float s0 = sigmoid_f(c[0]+bv.x), s1 = sigmoid_f(c[1]+bv.y);
                const float s2 = sigmoid_f(c[2]+bv.x), s3 = sigmoid_f(c[3]+bv.y);
                if (isR){
                    const float2 p1 = *(const float2*)(particles + (size_t)m1_*HH + nc);
                    const float2 p2 = *(const float2*)(particles + (size_t)m2_*HH + nc);
                    uint32_t h,l;
                    split2h(p1.x*s0, p1.y*s1, h, l);
                    *(uint32_t*)&g_XRhi[(size_t)m1_*HH+nc] = h;
                    *(uint32_t*)&g_XRlo[(size_t)m1_*HH+nc] = l;
                    split2h(p2.x*s2, p2.y*s3, h, l);
                    *(uint32_t*)&g_XRhi[(size_t)m2_*HH+nc] = h;
                    *(uint32_t*)&g_XRlo[(size_t)m2_*HH+nc] = l;
                } else {
                    *(float2*)(g_U + (size_t)m1_*HH + nc) = make_float2(s0, s1);
                    *(float2*)(g_U + (size_t)m2_*HH + nc) = make_float2(s2, s3);
                }
            } else if (MODE==2){
                const float2 u1 = *(const float2*)(g_U + (size_t)m1_*HH + nc);
                const float2 u2 = *(const float2*)(g_U + (size_t)m2_*HH + nc);
                const float2 p1 = *(const float2*)(particles + (size_t)m1_*HH + nc);
                const float2 p2 = *(const float2*)(particles + (size_t)m2_*HH + nc);
                float2 r1, r2;
                r1.x = (1.f-u1.x)*p1.x + u1.x*tanhf(c[0]+bv.x);
                r1.y = (1.f-u1.y)*p1.y + u1.y*tanhf(c[1]+bv.y);
                r2.x = (1.f-u2.x)*p2.x + u2.x*tanhf(c[2]+bv.x);
                r2.y = (1.f-u2.y)*p2.y + u2.y*tanhf(c[3]+bv.y);
                *(float2*)(g_NXT + (size_t)m1_*HH + nc) = r1;
                *(float2*)(g_NXT + (size_t)m2_*HH + nc) = r2;
                uint32_t h,l;
                split2h(r1.x, r1.y, h, l);
                *(uint32_t*)&g_NXhi[(size_t)m1_*HH+nc] = h;
                *(uint32_t*)&g_NXlo[(size_t)m1_*HH+nc] = l;
                split2h(r2.x, r2.y, h, l);
                *(uint32_t*)&g_NXhi[(size_t)m2_*HH+nc] = h;
                *(uint32_t*)&g_NXlo[(size_t)m2_*HH+nc] = l;
            } else {
                const float z0 = gelu_f(c[0]+bv.x), z1_ = gelu_f(c[1]+bv.y);
                const float z2 = gelu_f(c[2]+bv.x), z3 = gelu_f(c[3]+bv.y);
                uint32_t h,l;
                split2h(z0, z1_, h, l);
                *(uint32_t*)&g_Z1hi[(size_t)m1_*HH+nc] = h;
                *(uint32_t*)&g_Z1lo[(size_t)m1_*HH+nc] = l;
                split2h(z2, z3, h, l);
                *(uint32_t*)&g_Z1hi[(size_t)m2_*HH+nc] = h;
                *(uint32_t*)&g_Z1lo[(size_t)m2_*HH+nc] = l;
            }
        }
    }
}

// ---------------------------------------------------------------------------
__global__ void __launch_bounds__(NN) stage_weights_k(
    const float* __restrict__ weights,
    const float* __restrict__ uin,
    const float* __restrict__ b2,
    float* __restrict__ dout)
{
    __shared__ float sh[NN];
    const int b = blockIdx.x;
    const int n = threadIdx.x;
    const int m = b*NN + n;

    const float ll = g_llpart[m] + g_llpart[MM + m] + b2[0];
    const float lw = logf(weights[m] + 1e-10f) + ll;

    sh[n] = lw; __syncthreads();
    for (int s=512; s>0; s>>=1) { if (n<s) sh[n] = fmaxf(sh[n], sh[n+s]); __syncthreads(); }
    const float mx = sh[0]; __syncthreads();

    const float e = expf(lw - mx);
    sh[n] = e; __syncthreads();
    for (int s=512; s>0; s>>=1) { if (n<s) sh[n] += sh[n+s]; __syncthreads(); }
    const float S = sh[0]; __syncthreads();
    const float nw = e / S;

    sh[n] = nw*nw; __syncthreads();
    for (int s=512; s>0; s>>=1) { if (n<s) sh[n] += sh[n+s]; __syncthreads(); }
    const float ess = 1.0f / (sh[0] + 1e-10f); __syncthreads();
    const bool should = ess < 0.5f * (float)NN;

    float val = nw;
    sh[n] = val; __syncthreads();
    for (int off=1; off<NN; off<<=1) {
        float add = (n>=off) ? sh[n-off] : 0.f;
        __syncthreads();
        val += add;
        sh[n] = val;
        __syncthreads();
    }

    float pos = uin[b]*(1.0f/(float)NN) + (float)n*(1.0f/(float)NN);
    pos = fminf(pos, 0.9999f);
    int lo = 0, hi = NN;
    while (lo < hi) {
        int mid = (lo + hi) >> 1;
        if (sh[mid] < pos) lo = mid + 1; else hi = mid;
    }
    int idx = lo < (NN-1) ? lo : (NN-1);

    g_idx[m] = should ? idx : n;
    const float wf = should ? (1.0f/(float)NN) : nw;
    dout[8192 + (size_t)MM*HH + m] = wf;
    if (n == 0) dout[8192 + (size_t)MM*HH + MM + b] = ess;
}

__global__ void __launch_bounds__(HH) gather_belief_k(float* __restrict__ dout)
{
    const int b = blockIdx.y;
    const int chunk = blockIdx.x;
    const int h = threadIdx.x;
    const float* dw = dout + 8192 + (size_t)MM*HH;
    float* dnxt = dout + 8192;

    float accp = 0.f;
#pragma unroll
    for (int r=0; r<8; r++) {
        const int j = chunk*8 + r;
        const int src = g_idx[b*NN + j];
        const float v = g_NXT[(size_t)(b*NN + src)*HH + h];
        dnxt[(size_t)(b*NN + j)*HH + h] = v;
        accp = fmaf(v, dw[b*NN + j], accp);
    }
    g_partial[(b*128 + chunk)*HH + h] = accp;
}

__global__ void __launch_bounds__(HH) belief_reduce_k(float* __restrict__ dout)
{
    const int b = blockIdx.x;
    const int h = threadIdx.x;
    float s = 0.f;
    for (int c=0; c<128; c++) s += g_partial[(b*128 + c)*HH + h];
    dout[b*HH + h] = s;
}

// ---------------------------------------------------------------------------
extern "C" void kernel_launch(void* const* d_in, const int* in_sizes, int n_in,
                              void* d_out, int out_size)
{
    (void)in_sizes; (void)n_in; (void)out_size;
    const float* particles   = (const float*)d_in[0];
    const float* weights     = (const float*)d_in[1];
    const float* action      = (const float*)d_in[2];
    const float* observation = (const float*)d_in[3];
    const float* uin         = (const float*)d_in[4];
    const float* Wr = (const float*)d_in[5];  const float* br = (const float*)d_in[6];
    const float* Wu = (const float*)d_in[7];  const float* bu = (const float*)d_in[8];
    const float* Wc = (const float*)d_in[9];  const float* bc = (const float*)d_in[10];
    const float* W0 = (const float*)d_in[11]; const float* b0 = (const float*)d_in[12];
    const float* W1 = (const float*)d_in[13]; const float* b1 = (const float*)d_in[14];
    const float* W2 = (const float*)d_in[15]; const float* b2 = (const float*)d_in[16];
    float* out = (float*)d_out;

    cudaFuncSetAttribute(hmma_gemm_k<1>, cudaFuncAttributeMaxDynamicSharedMemorySize, SMEM_BYTES);
    cudaFuncSetAttribute(hmma_gemm_k<2>, cudaFuncAttributeMaxDynamicSharedMemorySize, SMEM_BYTES);
    cudaFuncSetAttribute(hmma_gemm_k<3>, cudaFuncAttributeMaxDynamicSharedMemorySize, SMEM_BYTES);
    cudaFuncSetAttribute(hmma_gemm_k<4>, cudaFuncAttributeMaxDynamicSharedMemorySize, SMEM_BYTES);

    wprep_k<<<dim3(16, 8, 5), dim3(32, 8)>>>(Wr, Wu, Wc, W0, W1);
    psplit_k<<<(MM*HH)/1024, 256>>>(particles);
    ssplit_k<<<1, 256>>>(action, observation);

    const dim3 blk(256);
    hmma_gemm_k<1><<<dim3(4, MM/128), blk, SMEM_BYTES>>>(particles, br, bu, bc, b0, b1, W2);
    hmma_gemm_k<2><<<dim3(2, MM/128), blk, SMEM_BYTES>>>(particles, br, bu, bc, b0, b1, W2);
    hmma_gemm_k<3><<<dim3(2, MM/128), blk, SMEM_BYTES>>>(particles, br, bu, bc, b0, b1, W2);
    hmma_gemm_k<4><<<dim3(2, MM/128), blk, SMEM_BYTES>>>(particles, br, bu, bc, b0, b1, W2);
    stage_weights_k<<<BB, NN>>>(weights, uin, b2, out);
    gather_belief_k<<<dim3(128, BB), HH>>>(out);
    belief_reduce_k<<<BB, HH>>>(out);
}

// round 7
// speedup vs baseline: 1.5178x; 1.1851x over previous
#include <cuda_runtime.h>
#include <cuda_fp16.h>
#include <cstdint>
#include <math.h>

#define BB 32
#define NN 1024
#define HH 256
#define AA 32
#define OO 256
#define MM (BB*NN)   // 32768 particle rows

// ---------------- scratch (static device arrays; no allocation) -------------
__device__ float g_U  [MM*HH];
__device__ float g_NXT[MM*HH];
__device__ float g_llpart[2*MM];
__device__ int   g_idx[MM];
__device__ float g_partial[BB*128*HH];

// fp16 A operands (single precision term)
__device__ __align__(128) __half g_P  [MM*HH];
__device__ __align__(128) __half g_XR [MM*HH];
__device__ __align__(128) __half g_NX [MM*HH];
__device__ __align__(128) __half g_Z1 [MM*HH];
__device__ __align__(128) __half g_ACT[BB*AA];
__device__ __align__(128) __half g_OBS[BB*OO];

#define WT_TOTAL 417792
__device__ __align__(128) __half g_WT[WT_TOTAL];
// offsets: Wr 0, Wu 73728, Wc 147456, W0 221184, W1 352256

__device__ __forceinline__ float sigmoid_f(float x){ return 1.0f/(1.0f+expf(-x)); }
__device__ __forceinline__ float gelu_f(float x){ return 0.5f*x*(1.0f+erff(x*0.70710678118654752f)); }

__device__ __forceinline__ uint32_t packh(float x, float y){
    __half hx = __float2half_rn(x), hy = __float2half_rn(y);
    return (uint32_t)__half_as_ushort(hx) | ((uint32_t)__half_as_ushort(hy) << 16);
}

__device__ __forceinline__ void mma16816(float* c, const uint32_t* a, uint32_t b0, uint32_t b1){
    asm volatile("mma.sync.aligned.m16n8k16.row.col.f32.f16.f16.f32 "
        "{%0,%1,%2,%3}, {%4,%5,%6,%7}, {%8,%9}, {%0,%1,%2,%3};"
        : "+f"(c[0]), "+f"(c[1]), "+f"(c[2]), "+f"(c[3])
        : "r"(a[0]), "r"(a[1]), "r"(a[2]), "r"(a[3]), "r"(b0), "r"(b1));
}

__device__ __forceinline__ uint32_t smem_u32(const void* p){
    uint32_t a;
    asm("{ .reg .u64 t; cvta.to.shared.u64 t, %1; cvt.u32.u64 %0, t; }" : "=r"(a) : "l"(p));
    return a;
}

#define CP16(dst, src) \
    asm volatile("cp.async.cg.shared.global [%0], [%1], 16;" :: "r"(dst), "l"(src) : "memory")
#define CP_COMMIT() asm volatile("cp.async.commit_group;" ::: "memory")
#define CP_WAIT1()  asm volatile("cp.async.wait_group 1;" ::: "memory")
#define CP_WAIT0()  asm volatile("cp.async.wait_group 0;" ::: "memory")
#define LDM4(r0,r1,r2,r3,addr) \
    asm volatile("ldmatrix.sync.aligned.m8n8.x4.shared.b16 {%0,%1,%2,%3}, [%4];" \
        : "=r"(r0),"=r"(r1),"=r"(r2),"=r"(r3) : "r"(addr))

#define PITCH 80
// stage: A 128*80=10240 | B 10240
#define OFF_B   10240
#define STAGE_STRIDE 20480
#define SMEM_BYTES  (2*STAGE_STRIDE)

// ---------------------------------------------------------------------------
// Prep kernels
// ---------------------------------------------------------------------------
__global__ void wprep_k(const float* __restrict__ Wr, const float* __restrict__ Wu,
                        const float* __restrict__ Wc, const float* __restrict__ W0,
                        const float* __restrict__ W1)
{
    const int mid = blockIdx.z;
    const int Ks[5] = {288,288,288,512,256};
    const size_t offs[5] = {0,73728,147456,221184,352256};
    const float* src = (mid==0)?Wr:(mid==1)?Wu:(mid==2)?Wc:(mid==3)?W0:W1;
    const int K = Ks[mid];
    const int k0 = blockIdx.x * 32;
    if (k0 >= K) return;
    const int n0 = blockIdx.y * 32;
    const int tx = threadIdx.x, ty = threadIdx.y;

    __shared__ float tile[32][33];
#pragma unroll
    for (int i=0;i<4;i++)
        tile[ty*4+i][tx] = src[(size_t)(k0+ty*4+i)*HH + n0 + tx];
    __syncthreads();
#pragma unroll
    for (int i=0;i<4;i++){
        const int r = ty*4+i;
        g_WT[offs[mid] + (size_t)(n0+r)*K + k0 + tx] = __float2half_rn(tile[tx][r]);
    }
}

__global__ void pconv_k(const float* __restrict__ p)
{
    const size_t i = ((size_t)blockIdx.x * 256 + threadIdx.x) * 4;
    float4 v = *(const float4*)(p + i);
    *(uint2*)&g_P[i] = make_uint2(packh(v.x, v.y), packh(v.z, v.w));
}

__global__ void sconv_k(const float* __restrict__ act, const float* __restrict__ obs)
{
    for (int i = threadIdx.x; i < BB*AA; i += 256)
        g_ACT[i] = __float2half_rn(act[i]);
    for (int i = threadIdx.x; i < BB*OO; i += 256)
        g_OBS[i] = __float2half_rn(obs[i]);
}

// ---------------------------------------------------------------------------
// HMMA GEMM: pure fp16, cp.async double-buffer, ldmatrix.
// CTA tile 128x128, 256 threads = 8 warps (4M x 2N), warp tile 32x64.
// ---------------------------------------------------------------------------
template<int MODE>
__device__ __forceinline__ void stage_panel(
    uint32_t buf, int p, int tid, int m0,
    const __half* __restrict__ a, const __half* __restrict__ t,
    const __half* __restrict__ w, int K)
{
    const int k0 = p * 32;
#pragma unroll
    for (int i=0;i<2;i++){
        const int idx = tid + i*256;
        const int row = idx >> 2, seg = idx & 3;
        const int k   = k0 + seg*8;
        const __half* s;
        if (MODE==4 || k < 256) s = a + (size_t)(m0+row)*HH + k;
        else                    s = t + (k - 256);
        CP16(buf + (uint32_t)(row*PITCH + seg*16), s);
    }
#pragma unroll
    for (int i=0;i<2;i++){
        const int idx = tid + i*256;
        const int row = idx >> 2, seg = idx & 3;
        CP16(buf + OFF_B + (uint32_t)(row*PITCH + seg*16), w + (size_t)row*K + k0 + seg*8);
    }
}

template<int MODE>
__global__ void __launch_bounds__(256, 2) hmma_gemm_k(
    const float* __restrict__ particles,
    const float* __restrict__ br, const float* __restrict__ bu,
    const float* __restrict__ bc, const float* __restrict__ b0,
    const float* __restrict__ b1, const float* __restrict__ W2)
{
    constexpr int K = (MODE==1 || MODE==2) ? 288 : (MODE==3 ? 512 : 256);
    constexpr int P = K / 32;

    extern __shared__ __align__(128) char smem[];
    __shared__ float red[128][2];
    const uint32_t sbase = smem_u32(smem);

    const int tid  = threadIdx.x;
    const int wid  = tid >> 5;
    const int lane = tid & 31;
    const int g    = lane >> 2;
    const int tig  = lane & 3;
    const int t8   = lane >> 3;
    const int r8   = lane & 7;
    const int warpM = wid >> 1;
    const int warpN = wid & 1;
    const int m0   = blockIdx.y * 128;
    const int bidx = blockIdx.y >> 3;

    size_t wt_off; int nw0;
    if (MODE==1){ wt_off = (blockIdx.x < 2) ? 0 : 73728; nw0 = (blockIdx.x & 1) * 128; }
    else if (MODE==2){ wt_off = 147456; nw0 = blockIdx.x * 128; }
    else if (MODE==3){ wt_off = 221184; nw0 = blockIdx.x * 128; }
    else             { wt_off = 352256; nw0 = blockIdx.x * 128; }

    const __half* a = (MODE==1) ? g_P : (MODE==2) ? g_XR : (MODE==3) ? g_NX : g_Z1;
    const __half* t = (MODE==3) ? (g_OBS + bidx*OO) : (g_ACT + bidx*AA);
    const __half* w = g_WT + wt_off + (size_t)nw0 * K;

    float acc[2][8][4];
#pragma unroll
    for (int i=0;i<2;i++)
#pragma unroll
        for (int j=0;j<8;j++)
#pragma unroll
            for (int q=0;q<4;q++) acc[i][j][q] = 0.f;

    stage_panel<MODE>(sbase,                0, tid, m0, a, t, w, K); CP_COMMIT();
    stage_panel<MODE>(sbase + STAGE_STRIDE, 1, tid, m0, a, t, w, K); CP_COMMIT();

#pragma unroll 1
    for (int p = 0; p < P; ++p){
        if (p + 1 < P) { CP_WAIT1(); } else { CP_WAIT0(); }
        __syncthreads();

        const uint32_t base = sbase + (p & 1) * STAGE_STRIDE;
        const uint32_t aS = base, bS = base + OFF_B;

#pragma unroll
        for (int ks = 0; ks < 2; ++ks){
            const int kkb = ks * 32;
            uint32_t ah[2][4];
#pragma unroll
            for (int mf = 0; mf < 2; ++mf){
                const uint32_t off = (uint32_t)((warpM*32 + mf*16 + (t8&1)*8 + r8)*PITCH
                                                + ((t8>>1)*8)*2 + kkb);
                LDM4(ah[mf][0],ah[mf][1],ah[mf][2],ah[mf][3], aS + off);
            }
#pragma unroll
            for (int q = 0; q < 4; ++q){
                const uint32_t boff = (uint32_t)((warpN*64 + q*16 + (t8>>1)*8 + r8)*PITCH
                                                 + ((t8&1)*8)*2 + kkb);
                uint32_t b0_,b1_,b2_,b3_;
                LDM4(b0_,b1_,b2_,b3_, bS + boff);
                mma16816(acc[0][2*q],   ah[0], b0_, b1_);
                mma16816(acc[1][2*q],   ah[1], b0_, b1_);
                mma16816(acc[0][2*q+1], ah[0], b2_, b3_);
                mma16816(acc[1][2*q+1], ah[1], b2_, b3_);
            }
        }
        __syncthreads();
        if (p + 2 < P){
            stage_panel<MODE>(sbase + (p & 1)*STAGE_STRIDE, p + 2, tid, m0, a, t, w, K);
            CP_COMMIT();
        }
    }

    // ---------------- epilogue ----------------
    if (MODE == 4){
        float pr[2][2] = {{0.f,0.f},{0.f,0.f}};
#pragma unroll
        for (int mf=0; mf<2; ++mf){
#pragma unroll
            for (int nf=0; nf<8; ++nf){
                const int nc = nw0 + warpN*64 + nf*8 + tig*2;
                const float2 bv = *(const float2*)(b1 + nc);
                const float2 wv = *(const float2*)(W2 + nc);
                float* c = acc[mf][nf];
                pr[mf][0] += gelu_f(c[0]+bv.x)*wv.x + gelu_f(c[1]+bv.y)*wv.y;
                pr[mf][1] += gelu_f(c[2]+bv.x)*wv.x + gelu_f(c[3]+bv.y)*wv.y;
            }
        }
#pragma unroll
        for (int mf=0; mf<2; ++mf)
#pragma unroll
            for (int rr=0; rr<2; ++rr){
                float v = pr[mf][rr];
                v += __shfl_xor_sync(0xffffffffu, v, 1);
                v += __shfl_xor_sync(0xffffffffu, v, 2);
                if (tig == 0) red[warpM*32 + mf*16 + rr*8 + g][warpN] = v;
            }
        __syncthreads();
        if (tid < 128)
            g_llpart[(size_t)blockIdx.x*MM + m0 + tid] = red[tid][0] + red[tid][1];
        return;
    }

    const float* bias;
    if (MODE==1) bias = (blockIdx.x<2) ? br : bu;
    else if (MODE==2) bias = bc;
    else bias = b0;
    const bool isR = (MODE==1) && (blockIdx.x < 2);

#pragma unroll
    for (int mf=0; mf<2; ++mf){
#pragma unroll
        for (int nf=0; nf<8; ++nf){
            const int nc = nw0 + warpN*64 + nf*8 + tig*2;
            const int m1_ = m0 + warpM*32 + mf*16 + g;
            const int m2_ = m1_ + 8;
            const float2 bv = *(const float2*)(bias + nc);
            float* c = acc[mf][nf];
            if (MODE==1){
                const float s0 = sigmoid_f(c[0]+bv.x), s1 = sigmoid_f(c[1]+bv.y);
                const float s2 = sigmoid_f(c[2]+bv.x), s3 = sigmoid_f(c[3]+bv.y);
                if (isR){
                    const float2 p1 = *(const float2*)(particles + (size_t)m1_*HH + nc);
                    const float2 p2 = *(const float2*)(particles + (size_t)m2_*HH + nc);
                    *(uint32_t*)&g_XR[(size_t)m1_*HH+nc] = packh(p1.x*s0, p1.y*s1);
                    *(uint32_t*)&g_XR[(size_t)m2_*HH+nc] = packh(p2.x*s2, p2.y*s3);
                } else {
                    *(float2*)(g_U + (size_t)m1_*HH + nc) = make_float2(s0, s1);
                    *(float2*)(g_U + (size_t)m2_*HH + nc) = make_float2(s2, s3);
                }
            } else if (MODE==2){
                const float2 u1 = *(const float2*)(g_U + (size_t)m1_*HH + nc);
                const float2 u2 = *(const float2*)(g_U + (size_t)m2_*HH + nc);
                const float2 p1 = *(const float2*)(particles + (size_t)m1_*HH + nc);
                const float2 p2 = *(const float2*)(particles + (size_t)m2_*HH + nc);
                float2 r1, r2;
                r1.x = (1.f-u1.x)*p1.x + u1.x*tanhf(c[0]+bv.x);
                r1.y = (1.f-u1.y)*p1.y + u1.y*tanhf(c[1]+bv.y);
                r2.x = (1.f-u2.x)*p2.x + u2.x*tanhf(c[2]+bv.x);
                r2.y = (1.f-u2.y)*p2.y + u2.y*tanhf(c[3]+bv.y);
                *(float2*)(g_NXT + (size_t)m1_*HH + nc) = r1;
                *(float2*)(g_NXT + (size_t)m2_*HH + nc) = r2;
                *(uint32_t*)&g_NX[(size_t)m1_*HH+nc] = packh(r1.x, r1.y);
                *(uint32_t*)&g_NX[(size_t)m2_*HH+nc] = packh(r2.x, r2.y);
            } else {
                const float z0 = gelu_f(c[0]+bv.x), z1_ = gelu_f(c[1]+bv.y);
                const float z2 = gelu_f(c[2]+bv.x), z3 = gelu_f(c[3]+bv.y);
                *(uint32_t*)&g_Z1[(size_t)m1_*HH+nc] = packh(z0, z1_);
                *(uint32_t*)&g_Z1[(size_t)m2_*HH+nc] = packh(z2, z3);
            }
        }
    }
}

// ---------------------------------------------------------------------------
__global__ void __launch_bounds__(NN) stage_weights_k(
    const float* __restrict__ weights,
    const float* __restrict__ uin,
    const float* __restrict__ b2,
    float* __restrict__ dout)
{
    __shared__ float sh[NN];
    const int b = blockIdx.x;
    const int n = threadIdx.x;
    const int m = b*NN + n;

    const float ll = g_llpart[m] + g_llpart[MM + m] + b2[0];
    const float lw = logf(weights[m] + 1e-10f) + ll;

    sh[n] = lw; __syncthreads();
    for (int s=512; s>0; s>>=1) { if (n<s) sh[n] = fmaxf(sh[n], sh[n+s]); __syncthreads(); }
    const float mx = sh[0]; __syncthreads();

    const float e = expf(lw - mx);
    sh[n] = e; __syncthreads();
    for (int s=512; s>0; s>>=1) { if (n<s) sh[n] += sh[n+s]; __syncthreads(); }
    const float S = sh[0]; __syncthreads();
    const float nw = e / S;

    sh[n] = nw*nw; __syncthreads();
    for (int s=512; s>0; s>>=1) { if (n<s) sh[n] += sh[n+s]; __syncthreads(); }
    const float ess = 1.0f / (sh[0] + 1e-10f); __syncthreads();
    const bool should = ess < 0.5f * (float)NN;

    float val = nw;
    sh[n] = val; __syncthreads();
    for (int off=1; off<NN; off<<=1) {
        float add = (n>=off) ? sh[n-off] : 0.f;
        __syncthreads();
        val += add;
        sh[n] = val;
        __syncthreads();
    }

    float pos = uin[b]*(1.0f/(float)NN) + (float)n*(1.0f/(float)NN);
    pos = fminf(pos, 0.9999f);
    int lo = 0, hi = NN;
    while (lo < hi) {
        int mid = (lo + hi) >> 1;
        if (sh[mid] < pos) lo = mid + 1; else hi = mid;
    }
    int idx = lo < (NN-1) ? lo : (NN-1);

    g_idx[m] = should ? idx : n;
    const float wf = should ? (1.0f/(float)NN) : nw;
    dout[8192 + (size_t)MM*HH + m] = wf;
    if (n == 0) dout[8192 + (size_t)MM*HH + MM + b] = ess;
}

__global__ void __launch_bounds__(HH) gather_belief_k(float* __restrict__ dout)
{
    const int b = blockIdx.y;
    const int chunk = blockIdx.x;
    const int h = threadIdx.x;
    const float* dw = dout + 8192 + (size_t)MM*HH;
    float* dnxt = dout + 8192;

    float accp = 0.f;
#pragma unroll
    for (int r=0; r<8; r++) {
        const int j = chunk*8 + r;
        const int src = g_idx[b*NN + j];
        const float v = g_NXT[(size_t)(b*NN + src)*HH + h];
        dnxt[(size_t)(b*NN + j)*HH + h] = v;
        accp = fmaf(v, dw[b*NN + j], accp);
    }
    g_partial[(b*128 + chunk)*HH + h] = accp;
}

__global__ void __launch_bounds__(HH) belief_reduce_k(float* __restrict__ dout)
{
    const int b = blockIdx.x;
    const int h = threadIdx.x;
    float s = 0.f;
    for (int c=0; c<128; c++) s += g_partial[(b*128 + c)*HH + h];
    dout[b*HH + h] = s;
}

// ---------------------------------------------------------------------------
extern "C" void kernel_launch(void* const* d_in, const int* in_sizes, int n_in,
                              void* d_out, int out_size)
{
    (void)in_sizes; (void)n_in; (void)out_size;
    const float* particles   = (const float*)d_in[0];
    const float* weights     = (const float*)d_in[1];
    const float* action      = (const float*)d_in[2];
    const float* observation = (const float*)d_in[3];
    const float* uin         = (const float*)d_in[4];
    const float* Wr = (const float*)d_in[5];  const float* br = (const float*)d_in[6];
    const float* Wu = (const float*)d_in[7];  const float* bu = (const float*)d_in[8];
    const float* Wc = (const float*)d_in[9];  const float* bc = (const float*)d_in[10];
    const float* W0 = (const float*)d_in[11]; const float* b0 = (const float*)d_in[12];
    const float* W1 = (const float*)d_in[13]; const float* b1 = (const float*)d_in[14];
    const float* W2 = (const float*)d_in[15]; const float* b2 = (const float*)d_in[16];
    float* out = (float*)d_out;

    cudaFuncSetAttribute(hmma_gemm_k<1>, cudaFuncAttributeMaxDynamicSharedMemorySize, SMEM_BYTES);
    cudaFuncSetAttribute(hmma_gemm_k<2>, cudaFuncAttributeMaxDynamicSharedMemorySize, SMEM_BYTES);
    cudaFuncSetAttribute(hmma_gemm_k<3>, cudaFuncAttributeMaxDynamicSharedMemorySize, SMEM_BYTES);
    cudaFuncSetAttribute(hmma_gemm_k<4>, cudaFuncAttributeMaxDynamicSharedMemorySize, SMEM_BYTES);

    wprep_k<<<dim3(16, 8, 5), dim3(32, 8)>>>(Wr, Wu, Wc, W0, W1);
    pconv_k<<<(MM*HH)/1024, 256>>>(particles);
    sconv_k<<<1, 256>>>(action, observation);

    const dim3 blk(256);
    hmma_gemm_k<1><<<dim3(4, MM/128), blk, SMEM_BYTES>>>(particles, br, bu, bc, b0, b1, W2);
    hmma_gemm_k<2><<<dim3(2, MM/128), blk, SMEM_BYTES>>>(particles, br, bu, bc, b0, b1, W2);
    hmma_gemm_k<3><<<dim3(2, MM/128), blk, SMEM_BYTES>>>(particles, br, bu, bc, b0, b1, W2);
    hmma_gemm_k<4><<<dim3(2, MM/128), blk, SMEM_BYTES>>>(particles, br, bu, bc, b0, b1, W2);
    stage_weights_k<<<BB, NN>>>(weights, uin, b2, out);
    gather_belief_k<<<dim3(128, BB), HH>>>(out);
    belief_reduce_k<<<BB, HH>>>(out);
}

// round 8
// speedup vs baseline: 1.5294x; 1.0076x over previous
#include <cuda_runtime.h>
#include <cuda_fp16.h>
#include <cstdint>
#include <math.h>

#define BB 32
#define NN 1024
#define HH 256
#define AA 32
#define OO 256
#define MM (BB*NN)   // 32768 particle rows

// ---------------- scratch (static device arrays; no allocation) -------------
__device__ float g_U  [MM*HH];
__device__ float g_NXT[MM*HH];
__device__ float g_llpart[2*MM];
__device__ int   g_idx[MM];
__device__ float g_partial[BB*128*HH];

// fp16 A operands
__device__ __align__(128) __half g_P  [MM*HH];
__device__ __align__(128) __half g_XR [MM*HH];
__device__ __align__(128) __half g_NX [MM*HH];
__device__ __align__(128) __half g_Z1 [MM*HH];
__device__ __align__(128) __half g_ACT[BB*AA];
__device__ __align__(128) __half g_OBS[BB*OO];

#define WT_TOTAL 417792
__device__ __align__(128) __half g_WT[WT_TOTAL];
// offsets: Wr 0, Wu 73728, Wc 147456, W0 221184, W1 352256

__device__ __forceinline__ float sigmoid_f(float x){ return 1.0f/(1.0f+expf(-x)); }
__device__ __forceinline__ float gelu_f(float x){ return 0.5f*x*(1.0f+erff(x*0.70710678118654752f)); }

__device__ __forceinline__ uint32_t packh(float x, float y){
    __half hx = __float2half_rn(x), hy = __float2half_rn(y);
    return (uint32_t)__half_as_ushort(hx) | ((uint32_t)__half_as_ushort(hy) << 16);
}

__device__ __forceinline__ void mma16816(float* c, const uint32_t* a, uint32_t b0, uint32_t b1){
    asm volatile("mma.sync.aligned.m16n8k16.row.col.f32.f16.f16.f32 "
        "{%0,%1,%2,%3}, {%4,%5,%6,%7}, {%8,%9}, {%0,%1,%2,%3};"
        : "+f"(c[0]), "+f"(c[1]), "+f"(c[2]), "+f"(c[3])
        : "r"(a[0]), "r"(a[1]), "r"(a[2]), "r"(a[3]), "r"(b0), "r"(b1));
}

__device__ __forceinline__ uint32_t smem_u32(const void* p){
    uint32_t a;
    asm("{ .reg .u64 t; cvta.to.shared.u64 t, %1; cvt.u32.u64 %0, t; }" : "=r"(a) : "l"(p));
    return a;
}

#define CP16(dst, src) \
    asm volatile("cp.async.cg.shared.global [%0], [%1], 16;" :: "r"(dst), "l"(src) : "memory")
#define CP_COMMIT() asm volatile("cp.async.commit_group;" ::: "memory")
#define CP_WAIT1()  asm volatile("cp.async.wait_group 1;" ::: "memory")
#define CP_WAIT0()  asm volatile("cp.async.wait_group 0;" ::: "memory")
#define LDM4(r0,r1,r2,r3,addr) \
    asm volatile("ldmatrix.sync.aligned.m8n8.x4.shared.b16 {%0,%1,%2,%3}, [%4];" \
        : "=r"(r0),"=r"(r1),"=r"(r2),"=r"(r3) : "r"(addr))

#define PITCH 80
// stage: A 128*80=10240 | B 10240
#define OFF_B   10240
#define STAGE_STRIDE 20480
#define NSTAGE 3
#define SMEM_BYTES  (NSTAGE*STAGE_STRIDE)

// ---------------------------------------------------------------------------
// Prep kernels
// ---------------------------------------------------------------------------
__global__ void wprep_k(const float* __restrict__ Wr, const float* __restrict__ Wu,
                        const float* __restrict__ Wc, const float* __restrict__ W0,
                        const float* __restrict__ W1)
{
    const int mid = blockIdx.z;
    const int Ks[5] = {288,288,288,512,256};
    const size_t offs[5] = {0,73728,147456,221184,352256};
    const float* src = (mid==0)?Wr:(mid==1)?Wu:(mid==2)?Wc:(mid==3)?W0:W1;
    const int K = Ks[mid];
    const int k0 = blockIdx.x * 32;
    if (k0 >= K) return;
    const int n0 = blockIdx.y * 32;
    const int tx = threadIdx.x, ty = threadIdx.y;

    __shared__ float tile[32][33];
#pragma unroll
    for (int i=0;i<4;i++)
        tile[ty*4+i][tx] = src[(size_t)(k0+ty*4+i)*HH + n0 + tx];
    __syncthreads();
#pragma unroll
    for (int i=0;i<4;i++){
        const int r = ty*4+i;
        g_WT[offs[mid] + (size_t)(n0+r)*K + k0 + tx] = __float2half_rn(tile[tx][r]);
    }
}

__global__ void pconv_k(const float* __restrict__ p)
{
    const size_t i = ((size_t)blockIdx.x * 256 + threadIdx.x) * 4;
    float4 v = *(const float4*)(p + i);
    *(uint2*)&g_P[i] = make_uint2(packh(v.x, v.y), packh(v.z, v.w));
}

__global__ void sconv_k(const float* __restrict__ act, const float* __restrict__ obs)
{
    for (int i = threadIdx.x; i < BB*AA; i += 256)
        g_ACT[i] = __float2half_rn(act[i]);
    for (int i = threadIdx.x; i < BB*OO; i += 256)
        g_OBS[i] = __float2half_rn(obs[i]);
}

// ---------------------------------------------------------------------------
// HMMA GEMM: pure fp16, 3-stage cp.async ring, ONE barrier per panel,
// staging issued before compute (overlap). CTA 128x128, 8 warps.
// ---------------------------------------------------------------------------
template<int MODE>
__device__ __forceinline__ void stage_panel(
    uint32_t buf, int p, int tid, int m0,
    const __half* __restrict__ a, const __half* __restrict__ t,
    const __half* __restrict__ w, int K)
{
    const int k0 = p * 32;
#pragma unroll
    for (int i=0;i<2;i++){
        const int idx = tid + i*256;
        const int row = idx >> 2, seg = idx & 3;
        const int k   = k0 + seg*8;
        const __half* s;
        if (MODE==4 || k < 256) s = a + (size_t)(m0+row)*HH + k;
        else                    s = t + (k - 256);
        CP16(buf + (uint32_t)(row*PITCH + seg*16), s);
    }
#pragma unroll
    for (int i=0;i<2;i++){
        const int idx = tid + i*256;
        const int row = idx >> 2, seg = idx & 3;
        CP16(buf + OFF_B + (uint32_t)(row*PITCH + seg*16), w + (size_t)row*K + k0 + seg*8);
    }
}

template<int MODE>
__global__ void __launch_bounds__(256, 2) hmma_gemm_k(
    const float* __restrict__ particles,
    const float* __restrict__ br, const float* __restrict__ bu,
    const float* __restrict__ bc, const float* __restrict__ b0,
    const float* __restrict__ b1, const float* __restrict__ W2)
{
    constexpr int K = (MODE==1 || MODE==2) ? 288 : (MODE==3 ? 512 : 256);
    constexpr int P = K / 32;

    extern __shared__ __align__(128) char smem[];
    __shared__ float red[128][2];
    const uint32_t sbase = smem_u32(smem);

    const int tid  = threadIdx.x;
    const int wid  = tid >> 5;
    const int lane = tid & 31;
    const int g    = lane >> 2;
    const int tig  = lane & 3;
    const int t8   = lane >> 3;
    const int r8   = lane & 7;
    const int warpM = wid >> 1;
    const int warpN = wid & 1;
    const int m0   = blockIdx.y * 128;
    const int bidx = blockIdx.y >> 3;

    size_t wt_off; int nw0;
    if (MODE==1){ wt_off = (blockIdx.x < 2) ? 0 : 73728; nw0 = (blockIdx.x & 1) * 128; }
    else if (MODE==2){ wt_off = 147456; nw0 = blockIdx.x * 128; }
    else if (MODE==3){ wt_off = 221184; nw0 = blockIdx.x * 128; }
    else             { wt_off = 352256; nw0 = blockIdx.x * 128; }

    const __half* a = (MODE==1) ? g_P : (MODE==2) ? g_XR : (MODE==3) ? g_NX : g_Z1;
    const __half* t = (MODE==3) ? (g_OBS + bidx*OO) : (g_ACT + bidx*AA);
    const __half* w = g_WT + wt_off + (size_t)nw0 * K;

    float acc[2][8][4];
#pragma unroll
    for (int i=0;i<2;i++)
#pragma unroll
        for (int j=0;j<8;j++)
#pragma unroll
            for (int q=0;q<4;q++) acc[i][j][q] = 0.f;

    stage_panel<MODE>(sbase + 0*STAGE_STRIDE, 0, tid, m0, a, t, w, K); CP_COMMIT();
    stage_panel<MODE>(sbase + 1*STAGE_STRIDE, 1, tid, m0, a, t, w, K); CP_COMMIT();

    int slot = 0, wslot = 2;
#pragma unroll 1
    for (int p = 0; p < P; ++p){
        if (p + 1 < P) { CP_WAIT1(); } else { CP_WAIT0(); }
        __syncthreads();   // stage p visible to all; all done computing old slot wslot

        // issue next stage FIRST: overlaps with compute below
        if (p + 2 < P){
            stage_panel<MODE>(sbase + wslot*STAGE_STRIDE, p + 2, tid, m0, a, t, w, K);
            CP_COMMIT();
        }

        const uint32_t base = sbase + slot * STAGE_STRIDE;
        const uint32_t aS = base, bS = base + OFF_B;

#pragma unroll
        for (int ks = 0; ks < 2; ++ks){
            const int kkb = ks * 32;
            uint32_t ah[2][4];
#pragma unroll
            for (int mf = 0; mf < 2; ++mf){
                const uint32_t off = (uint32_t)((warpM*32 + mf*16 + (t8&1)*8 + r8)*PITCH
                                                + ((t8>>1)*8)*2 + kkb);
                LDM4(ah[mf][0],ah[mf][1],ah[mf][2],ah[mf][3], aS + off);
            }
#pragma unroll
            for (int q = 0; q < 4; ++q){
                const uint32_t boff = (uint32_t)((warpN*64 + q*16 + (t8>>1)*8 + r8)*PITCH
                                                 + ((t8&1)*8)*2 + kkb);
                uint32_t b0_,b1_,b2_,b3_;
                LDM4(b0_,b1_,b2_,b3_, bS + boff);
                mma16816(acc[0][2*q],   ah[0], b0_, b1_);
                mma16816(acc[1][2*q],   ah[1], b0_, b1_);
                mma16816(acc[0][2*q+1], ah[0], b2_, b3_);
                mma16816(acc[1][2*q+1], ah[1], b2_, b3_);
            }
        }
        slot  = (slot  + 1 == NSTAGE) ? 0 : slot  + 1;
        wslot = (wslot + 1 == NSTAGE) ? 0 : wslot + 1;
    }

    // ---------------- epilogue ----------------
    if (MODE == 4){
        float pr[2][2] = {{0.f,0.f},{0.f,0.f}};
#pragma unroll
        for (int mf=0; mf<2; ++mf){
#pragma unroll
            for (int nf=0; nf<8; ++nf){
                const int nc = nw0 + warpN*64 + nf*8 + tig*2;
                const float2 bv = *(const float2*)(b1 + nc);
                const float2 wv = *(const float2*)(W2 + nc);
                float* c = acc[mf][nf];
                pr[mf][0] += gelu_f(c[0]+bv.x)*wv.x + gelu_f(c[1]+bv.y)*wv.y;
                pr[mf][1] += gelu_f(c[2]+bv.x)*wv.x + gelu_f(c[3]+bv.y)*wv.y;
            }
        }
#pragma unroll
        for (int mf=0; mf<2; ++mf)
#pragma unroll
            for (int rr=0; rr<2; ++rr){
                float v = pr[mf][rr];
                v += __shfl_xor_sync(0xffffffffu, v, 1);
                v += __shfl_xor_sync(0xffffffffu, v, 2);
                if (tig == 0) red[warpM*32 + mf*16 + rr*8 + g][warpN] = v;
            }
        __syncthreads();
        if (tid < 128)
            g_llpart[(size_t)blockIdx.x*MM + m0 + tid] = red[tid][0] + red[tid][1];
        return;
    }

    const float* bias;
    if (MODE==1) bias = (blockIdx.x<2) ? br : bu;
    else if (MODE==2) bias = bc;
    else bias = b0;
    const bool isR = (MODE==1) && (blockIdx.x < 2);

#pragma unroll
    for (int mf=0; mf<2; ++mf){
#pragma unroll
        for (int nf=0; nf<8; ++nf){
            const int nc = nw0 + warpN*64 + nf*8 + tig*2;
            const int m1_ = m0 + warpM*32 + mf*16 + g;
            const int m2_ = m1_ + 8;
            const float2 bv = *(const float2*)(bias + nc);
            float* c = acc[mf][nf];
            if (MODE==1){
                const float s0 = sigmoid_f(c[0]+bv.x), s1 = sigmoid_f(c[1]+bv.y);
                const float s2 = sigmoid_f(c[2]+bv.x), s3 = sigmoid_f(c[3]+bv.y);
                if (isR){
                    const float2 p1 = *(const float2*)(particles + (size_t)m1_*HH + nc);
                    const float2 p2 = *(const float2*)(particles + (size_t)m2_*HH + nc);
                    *(uint32_t*)&g_XR[(size_t)m1_*HH+nc] = packh(p1.x*s0, p1.y*s1);
                    *(uint32_t*)&g_XR[(size_t)m2_*HH+nc] = packh(p2.x*s2, p2.y*s3);
                } else {
                    *(float2*)(g_U + (size_t)m1_*HH + nc) = make_float2(s0, s1);
                    *(float2*)(g_U + (size_t)m2_*HH + nc) = make_float2(s2, s3);
                }
            } else if (MODE==2){
                const float2 u1 = *(const float2*)(g_U + (size_t)m1_*HH + nc);
                const float2 u2 = *(const float2*)(g_U + (size_t)m2_*HH + nc);
                const float2 p1 = *(const float2*)(particles + (size_t)m1_*HH + nc);
                const float2 p2 = *(const float2*)(particles + (size_t)m2_*HH + nc);
                float2 r1, r2;
                r1.x = (1.f-u1.x)*p1.x + u1.x*tanhf(c[0]+bv.x);
                r1.y = (1.f-u1.y)*p1.y + u1.y*tanhf(c[1]+bv.y);
                r2.x = (1.f-u2.x)*p2.x + u2.x*tanhf(c[2]+bv.x);
                r2.y = (1.f-u2.y)*p2.y + u2.y*tanhf(c[3]+bv.y);
                *(float2*)(g_NXT + (size_t)m1_*HH + nc) = r1;
                *(float2*)(g_NXT + (size_t)m2_*HH + nc) = r2;
                *(uint32_t*)&g_NX[(size_t)m1_*HH+nc] = packh(r1.x, r1.y);
                *(uint32_t*)&g_NX[(size_t)m2_*HH+nc] = packh(r2.x, r2.y);
            } else {
                const float z0 = gelu_f(c[0]+bv.x), z1_ = gelu_f(c[1]+bv.y);
                const float z2 = gelu_f(c[2]+bv.x), z3 = gelu_f(c[3]+bv.y);
                *(uint32_t*)&g_Z1[(size_t)m1_*HH+nc] = packh(z0, z1_);
                *(uint32_t*)&g_Z1[(size_t)m2_*HH+nc] = packh(z2, z3);
            }
        }
    }
}

// ---------------------------------------------------------------------------
__global__ void __launch_bounds__(NN) stage_weights_k(
    const float* __restrict__ weights,
    const float* __restrict__ uin,
    const float* __restrict__ b2,
    float* __restrict__ dout)
{
    __shared__ float sh[NN];
    const int b = blockIdx.x;
    const int n = threadIdx.x;
    const int m = b*NN + n;

    const float ll = g_llpart[m] + g_llpart[MM + m] + b2[0];
    const float lw = logf(weights[m] + 1e-10f) + ll;

    sh[n] = lw; __syncthreads();
    for (int s=512; s>0; s>>=1) { if (n<s) sh[n] = fmaxf(sh[n], sh[n+s]); __syncthreads(); }
    const float mx = sh[0]; __syncthreads();

    const float e = expf(lw - mx);
    sh[n] = e; __syncthreads();
    for (int s=512; s>0; s>>=1) { if (n<s) sh[n] += sh[n+s]; __syncthreads(); }
    const float S = sh[0]; __syncthreads();
    const float nw = e / S;

    sh[n] = nw*nw; __syncthreads();
    for (int s=512; s>0; s>>=1) { if (n<s) sh[n] += sh[n+s]; __syncthreads(); }
    const float ess = 1.0f / (sh[0] + 1e-10f); __syncthreads();
    const bool should = ess < 0.5f * (float)NN;

    float val = nw;
    sh[n] = val; __syncthreads();
    for (int off=1; off<NN; off<<=1) {
        float add = (n>=off) ? sh[n-off] : 0.f;
        __syncthreads();
        val += add;
        sh[n] = val;
        __syncthreads();
    }

    float pos = uin[b]*(1.0f/(float)NN) + (float)n*(1.0f/(float)NN);
    pos = fminf(pos, 0.9999f);
    int lo = 0, hi = NN;
    while (lo < hi) {
        int mid = (lo + hi) >> 1;
        if (sh[mid] < pos) lo = mid + 1; else hi = mid;
    }
    int idx = lo < (NN-1) ? lo : (NN-1);

    g_idx[m] = should ? idx : n;
    const float wf = should ? (1.0f/(float)NN) : nw;
    dout[8192 + (size_t)MM*HH + m] = wf;
    if (n == 0) dout[8192 + (size_t)MM*HH + MM + b] = ess;
}

__global__ void __launch_bounds__(HH) gather_belief_k(float* __restrict__ dout)
{
    const int b = blockIdx.y;
    const int chunk = blockIdx.x;
    const int h = threadIdx.x;
    const float* dw = dout + 8192 + (size_t)MM*HH;
    float* dnxt = dout + 8192;

    float accp = 0.f;
#pragma unroll
    for (int r=0; r<8; r++) {
        const int j = chunk*8 + r;
        const int src = g_idx[b*NN + j];
        const float v = g_NXT[(size_t)(b*NN + src)*HH + h];
        dnxt[(size_t)(b*NN + j)*HH + h] = v;
        accp = fmaf(v, dw[b*NN + j], accp);
    }
    g_partial[(b*128 + chunk)*HH + h] = accp;
}

__global__ void __launch_bounds__(HH) belief_reduce_k(float* __restrict__ dout)
{
    const int b = blockIdx.x;
    const int h = threadIdx.x;
    float s = 0.f;
    for (int c=0; c<128; c++) s += g_partial[(b*128 + c)*HH + h];
    dout[b*HH + h] = s;
}

// ---------------------------------------------------------------------------
extern "C" void kernel_launch(void* const* d_in, const int* in_sizes, int n_in,
                              void* d_out, int out_size)
{
    (void)in_sizes; (void)n_in; (void)out_size;
    const float* particles   = (const float*)d_in[0];
    const float* weights     = (const float*)d_in[1];
    const float* action      = (const float*)d_in[2];
    const float* observation = (const float*)d_in[3];
    const float* uin         = (const float*)d_in[4];
    const float* Wr = (const float*)d_in[5];  const float* br = (const float*)d_in[6];
    const float* Wu = (const float*)d_in[7];  const float* bu = (const float*)d_in[8];
    const float* Wc = (const float*)d_in[9];  const float* bc = (const float*)d_in[10];
    const float* W0 = (const float*)d_in[11]; const float* b0 = (const float*)d_in[12];
    const float* W1 = (const float*)d_in[13]; const float* b1 = (const float*)d_in[14];
    const float* W2 = (const float*)d_in[15]; const float* b2 = (const float*)d_in[16];
    float* out = (float*)d_out;

    cudaFuncSetAttribute(hmma_gemm_k<1>, cudaFuncAttributeMaxDynamicSharedMemorySize, SMEM_BYTES);
    cudaFuncSetAttribute(hmma_gemm_k<2>, cudaFuncAttributeMaxDynamicSharedMemorySize, SMEM_BYTES);
    cudaFuncSetAttribute(hmma_gemm_k<3>, cudaFuncAttributeMaxDynamicSharedMemorySize, SMEM_BYTES);
    cudaFuncSetAttribute(hmma_gemm_k<4>, cudaFuncAttributeMaxDynamicSharedMemorySize, SMEM_BYTES);

    wprep_k<<<dim3(16, 8, 5), dim3(32, 8)>>>(Wr, Wu, Wc, W0, W1);
    pconv_k<<<(MM*HH)/1024, 256>>>(particles);
    sconv_k<<<1, 256>>>(action, observation);

    const dim3 blk(256);
    hmma_gemm_k<1><<<dim3(4, MM/128), blk, SMEM_BYTES>>>(particles, br, bu, bc, b0, b1, W2);
    hmma_gemm_k<2><<<dim3(2, MM/128), blk, SMEM_BYTES>>>(particles, br, bu, bc, b0, b1, W2);
    hmma_gemm_k<3><<<dim3(2, MM/128), blk, SMEM_BYTES>>>(particles, br, bu, bc, b0, b1, W2);
    hmma_gemm_k<4><<<dim3(2, MM/128), blk, SMEM_BYTES>>>(particles, br, bu, bc, b0, b1, W2);
    stage_weights_k<<<BB, NN>>>(weights, uin, b2, out);
    gather_belief_k<<<dim3(128, BB), HH>>>(out);
    belief_reduce_k<<<BB, HH>>>(out);
}